// round 3
// baseline (speedup 1.0000x reference)
#include <cuda_runtime.h>
#include <cstdint>

#define N_NODES_MAX 100000
#define NFEAT 64
#define NCLASS 16

// Scratch for aggregation result (+ (1+eps)*x folded in). 25.6 MB.
__device__ float g_agg[N_NODES_MAX * NFEAT];

// ---------------------------------------------------------------------------
// Kernel 1: agg = (1 + eps) * x     (vectorized float4 streaming pass)
// ---------------------------------------------------------------------------
__global__ void init_agg_kernel(const float* __restrict__ x,
                                const float* __restrict__ eps,
                                float* __restrict__ agg,
                                int n_vec4) {
    int i = blockIdx.x * blockDim.x + threadIdx.x;
    if (i >= n_vec4) return;
    float s = 1.0f + *eps;
    float4 v = reinterpret_cast<const float4*>(x)[i];
    v.x *= s; v.y *= s; v.z *= s; v.w *= s;
    reinterpret_cast<float4*>(agg)[i] = v;
}

// ---------------------------------------------------------------------------
// Kernel 2: scatter-add.  16 threads per edge, each handles 4 features via
// LDG.128 gather + red.global.add.v4.f32 (vectorized L2 reduction).
// edge_index is int32 (JAX default x64-disabled): row0 = src, row1 = dst.
// ---------------------------------------------------------------------------
__global__ void scatter_kernel(const float* __restrict__ x,
                               const int* __restrict__ edge_index,
                               float* __restrict__ agg,
                               int n_edges, int n_nodes) {
    int gid = blockIdx.x * blockDim.x + threadIdx.x;
    int e  = gid >> 4;            // 16 lanes per edge
    int fg = (gid & 15) << 2;     // feature offset: 0,4,...,60
    if (e >= n_edges) return;
    int src = edge_index[e];
    int dst = edge_index[n_edges + e];
    if ((unsigned)src >= (unsigned)n_nodes || (unsigned)dst >= (unsigned)n_nodes) return;
    float4 v = *reinterpret_cast<const float4*>(x + (long long)src * NFEAT + fg);
    float* p = agg + (long long)dst * NFEAT + fg;
    asm volatile("red.global.add.v4.f32 [%0], {%1,%2,%3,%4};"
                 :: "l"(p), "f"(v.x), "f"(v.y), "f"(v.z), "f"(v.w)
                 : "memory");
}

// ---------------------------------------------------------------------------
// Kernel 3: MLP.  out = relu(h @ W1 + b1) @ W2 + b2, one node per thread.
// W1 staged transposed in shared so the K-loop reads contiguous float4
// broadcasts (conflict-free).  FMA-bound by design.
// ---------------------------------------------------------------------------
__global__ __launch_bounds__(128)
void mlp_kernel(const float* __restrict__ agg,
                const float* __restrict__ W1,   // [64,64] row-major (k, j)
                const float* __restrict__ b1,   // [64]
                const float* __restrict__ W2,   // [64,16] row-major (j, c)
                const float* __restrict__ b2,   // [16]
                float* __restrict__ out,        // [n,16]
                int n_nodes) {
    __shared__ float sW1T[NFEAT * NFEAT];   // [j][k]  (transposed)
    __shared__ float sW2[NFEAT * NCLASS];   // [j][c]
    __shared__ float sb1[NFEAT];
    __shared__ float sb2[NCLASS];

    for (int i = threadIdx.x; i < NFEAT * NFEAT; i += blockDim.x) {
        int k = i >> 6, j = i & 63;
        sW1T[j * NFEAT + k] = W1[i];
    }
    for (int i = threadIdx.x; i < NFEAT * NCLASS; i += blockDim.x) sW2[i] = W2[i];
    if (threadIdx.x < NFEAT)  sb1[threadIdx.x] = b1[threadIdx.x];
    if (threadIdx.x < NCLASS) sb2[threadIdx.x] = b2[threadIdx.x];
    __syncthreads();

    int node = blockIdx.x * blockDim.x + threadIdx.x;
    if (node >= n_nodes) return;

    // Load this node's aggregated features into registers (64 floats).
    float4 h[16];
    const float4* row = reinterpret_cast<const float4*>(agg + (long long)node * NFEAT);
#pragma unroll
    for (int i = 0; i < 16; i++) h[i] = row[i];

    float acc[NCLASS];
#pragma unroll
    for (int c = 0; c < NCLASS; c++) acc[c] = sb2[c];

#pragma unroll 4
    for (int j = 0; j < NFEAT; j++) {
        // hidden_j = relu(b1[j] + sum_k h[k] * W1[k][j])
        float h0 = 0.f, h1 = 0.f, h2 = 0.f, h3 = 0.f;   // 4-way ILP chains
        const float4* wrow = reinterpret_cast<const float4*>(sW1T + j * NFEAT);
#pragma unroll
        for (int i = 0; i < 16; i++) {
            float4 w = wrow[i];
            h0 = fmaf(h[i].x, w.x, h0);
            h1 = fmaf(h[i].y, w.y, h1);
            h2 = fmaf(h[i].z, w.z, h2);
            h3 = fmaf(h[i].w, w.w, h3);
        }
        float hid = fmaxf(sb1[j] + (h0 + h1) + (h2 + h3), 0.0f);

        const float4* w2row = reinterpret_cast<const float4*>(sW2 + j * NCLASS);
#pragma unroll
        for (int c = 0; c < 4; c++) {
            float4 w2 = w2row[c];
            acc[4 * c + 0] = fmaf(hid, w2.x, acc[4 * c + 0]);
            acc[4 * c + 1] = fmaf(hid, w2.y, acc[4 * c + 1]);
            acc[4 * c + 2] = fmaf(hid, w2.z, acc[4 * c + 2]);
            acc[4 * c + 3] = fmaf(hid, w2.w, acc[4 * c + 3]);
        }
    }

    float4* o = reinterpret_cast<float4*>(out + (long long)node * NCLASS);
#pragma unroll
    for (int c = 0; c < 4; c++)
        o[c] = make_float4(acc[4 * c], acc[4 * c + 1], acc[4 * c + 2], acc[4 * c + 3]);
}

// ---------------------------------------------------------------------------
// Launch.  Inputs (metadata order): x, edge_index(int32), eps, W1, b1, W2, b2
// ---------------------------------------------------------------------------
extern "C" void kernel_launch(void* const* d_in, const int* in_sizes, int n_in,
                              void* d_out, int out_size) {
    const float* x   = (const float*)d_in[0];
    const int*   ei  = (const int*)d_in[1];
    const float* eps = (const float*)d_in[2];
    const float* W1  = (const float*)d_in[3];
    const float* b1  = (const float*)d_in[4];
    const float* W2  = (const float*)d_in[5];
    const float* b2  = (const float*)d_in[6];
    float*       out = (float*)d_out;

    int n_nodes = in_sizes[0] / NFEAT;
    int n_edges = in_sizes[1] / 2;

    float* agg;
    cudaGetSymbolAddress((void**)&agg, g_agg);

    // 1) agg = (1+eps) * x
    int n_vec4 = (n_nodes * NFEAT) / 4;
    init_agg_kernel<<<(n_vec4 + 255) / 256, 256>>>(x, eps, agg, n_vec4);

    // 2) agg[dst] += x[src]  (vectorized L2 atomics)
    long long total_threads = (long long)n_edges * 16;
    int blocks = (int)((total_threads + 255) / 256);
    scatter_kernel<<<blocks, 256>>>(x, ei, agg, n_edges, n_nodes);

    // 3) out = relu(agg @ W1 + b1) @ W2 + b2
    mlp_kernel<<<(n_nodes + 127) / 128, 128>>>(agg, W1, b1, W2, b2, out, n_nodes);
}

// round 4
// speedup vs baseline: 1.0759x; 1.0759x over previous
#include <cuda_runtime.h>
#include <cstdint>

#define N_NODES_MAX 100000
#define N_EDGES_MAX 1700000
#define NFEAT 64
#define NCLASS 16
#define SCAN_B 512

// Scratch (device globals — no allocation allowed in kernel_launch).
__device__ float g_agg[N_NODES_MAX * NFEAT];          // 25.6 MB
__device__ int   g_counts[N_NODES_MAX + 1];
__device__ int   g_row_start[N_NODES_MAX + 1];
__device__ int   g_cursor[N_NODES_MAX];
__device__ int   g_csr_src[N_EDGES_MAX];              // 6.8 MB
__device__ int   g_bsum[1024];
__device__ int   g_bpre[1024];

// ---------------------------------------------------------------------------
// CSR build: zero -> histogram(dst) -> 3-phase exclusive scan -> permute
// ---------------------------------------------------------------------------
__global__ void zero_counts_kernel(int* __restrict__ counts, int n) {
    int i = blockIdx.x * blockDim.x + threadIdx.x;
    if (i < n) counts[i] = 0;
}

__global__ void hist_kernel(const int* __restrict__ edge_index,
                            int* __restrict__ counts,
                            int n_edges, int n_nodes) {
    int e = blockIdx.x * blockDim.x + threadIdx.x;
    if (e >= n_edges) return;
    int dst = edge_index[n_edges + e];
    if ((unsigned)dst < (unsigned)n_nodes) atomicAdd(&counts[dst], 1);
}

__global__ void scan1_kernel(const int* __restrict__ counts,
                             int* __restrict__ bsum, int n) {
    __shared__ int sh[SCAN_B];
    int i = blockIdx.x * SCAN_B + threadIdx.x;
    sh[threadIdx.x] = (i < n) ? counts[i] : 0;
    __syncthreads();
    for (int off = SCAN_B / 2; off > 0; off >>= 1) {
        if (threadIdx.x < off) sh[threadIdx.x] += sh[threadIdx.x + off];
        __syncthreads();
    }
    if (threadIdx.x == 0) bsum[blockIdx.x] = sh[0];
}

__global__ void scan2_kernel(const int* __restrict__ bsum,
                             int* __restrict__ bpre, int nb) {
    if (threadIdx.x == 0 && blockIdx.x == 0) {
        int run = 0;
        for (int b = 0; b < nb; b++) { bpre[b] = run; run += bsum[b]; }
    }
}

__global__ void scan3_kernel(const int* __restrict__ counts,
                             const int* __restrict__ bpre,
                             int* __restrict__ row_start,
                             int* __restrict__ cursor, int n) {
    __shared__ int sh[SCAN_B];
    int i = blockIdx.x * SCAN_B + threadIdx.x;
    int v = (i < n) ? counts[i] : 0;
    sh[threadIdx.x] = v;
    __syncthreads();
    // Hillis-Steele inclusive scan
    for (int off = 1; off < SCAN_B; off <<= 1) {
        int t = (threadIdx.x >= off) ? sh[threadIdx.x - off] : 0;
        __syncthreads();
        sh[threadIdx.x] += t;
        __syncthreads();
    }
    int excl = sh[threadIdx.x] - v + bpre[blockIdx.x];
    if (i < n) {
        row_start[i] = excl;
        cursor[i]    = excl;
        if (i == n - 1) row_start[n] = excl + v;
    }
}

__global__ void permute_kernel(const int* __restrict__ edge_index,
                               int* __restrict__ cursor,
                               int* __restrict__ csr_src,
                               int n_edges, int n_nodes) {
    int e = blockIdx.x * blockDim.x + threadIdx.x;
    if (e >= n_edges) return;
    int src = edge_index[e];
    int dst = edge_index[n_edges + e];
    if ((unsigned)src >= (unsigned)n_nodes || (unsigned)dst >= (unsigned)n_nodes) return;
    int pos = atomicAdd(&cursor[dst], 1);
    csr_src[pos] = src;
}

// ---------------------------------------------------------------------------
// Pull-based gather: agg[node] = (1+eps)*x[node] + sum_{src in N(node)} x[src]
// 16 lanes per node (4 feats each). src ids fetched 16-at-a-time and
// broadcast via shfl. No atomics; single write per output element.
// ---------------------------------------------------------------------------
__global__ __launch_bounds__(256)
void gather_kernel(const float* __restrict__ x,
                   const int* __restrict__ row_start,
                   const int* __restrict__ csr_src,
                   const float* __restrict__ eps,
                   float* __restrict__ agg,
                   int n_nodes) {
    int gid  = blockIdx.x * blockDim.x + threadIdx.x;
    int slot = gid >> 4;
    int lane = gid & 15;
    int fg   = lane << 2;
    int node = min(slot, n_nodes - 1);   // keep all 32 lanes active for shfl

    int beg = row_start[node];
    int end = row_start[node + 1];

    float s = 1.0f + *eps;
    float4 acc = *reinterpret_cast<const float4*>(x + (long long)node * NFEAT + fg);
    acc.x *= s; acc.y *= s; acc.z *= s; acc.w *= s;

    for (int e = beg; e < end; ) {
        int cnt = min(16, end - e);
        int id = (lane < cnt) ? csr_src[e + lane] : 0;
#pragma unroll 4
        for (int j = 0; j < cnt; j++) {
            int src = __shfl_sync(0xffffffffu, id, j, 16);
            float4 v = *reinterpret_cast<const float4*>(x + (long long)src * NFEAT + fg);
            acc.x += v.x; acc.y += v.y; acc.z += v.z; acc.w += v.w;
        }
        e += cnt;
    }

    if (slot < n_nodes)
        *reinterpret_cast<float4*>(agg + (long long)node * NFEAT + fg) = acc;
}

// ---------------------------------------------------------------------------
// MLP: out = relu(h @ W1 + b1) @ W2 + b2, one node per thread.
// ---------------------------------------------------------------------------
__global__ __launch_bounds__(128)
void mlp_kernel(const float* __restrict__ agg,
                const float* __restrict__ W1,
                const float* __restrict__ b1,
                const float* __restrict__ W2,
                const float* __restrict__ b2,
                float* __restrict__ out,
                int n_nodes) {
    __shared__ float sW1T[NFEAT * NFEAT];
    __shared__ float sW2[NFEAT * NCLASS];
    __shared__ float sb1[NFEAT];
    __shared__ float sb2[NCLASS];

    for (int i = threadIdx.x; i < NFEAT * NFEAT; i += blockDim.x) {
        int k = i >> 6, j = i & 63;
        sW1T[j * NFEAT + k] = W1[i];
    }
    for (int i = threadIdx.x; i < NFEAT * NCLASS; i += blockDim.x) sW2[i] = W2[i];
    if (threadIdx.x < NFEAT)  sb1[threadIdx.x] = b1[threadIdx.x];
    if (threadIdx.x < NCLASS) sb2[threadIdx.x] = b2[threadIdx.x];
    __syncthreads();

    int node = blockIdx.x * blockDim.x + threadIdx.x;
    if (node >= n_nodes) return;

    float4 h[16];
    const float4* row = reinterpret_cast<const float4*>(agg + (long long)node * NFEAT);
#pragma unroll
    for (int i = 0; i < 16; i++) h[i] = row[i];

    float acc[NCLASS];
#pragma unroll
    for (int c = 0; c < NCLASS; c++) acc[c] = sb2[c];

#pragma unroll 4
    for (int j = 0; j < NFEAT; j++) {
        float h0 = 0.f, h1 = 0.f, h2 = 0.f, h3 = 0.f;
        const float4* wrow = reinterpret_cast<const float4*>(sW1T + j * NFEAT);
#pragma unroll
        for (int i = 0; i < 16; i++) {
            float4 w = wrow[i];
            h0 = fmaf(h[i].x, w.x, h0);
            h1 = fmaf(h[i].y, w.y, h1);
            h2 = fmaf(h[i].z, w.z, h2);
            h3 = fmaf(h[i].w, w.w, h3);
        }
        float hid = fmaxf(sb1[j] + (h0 + h1) + (h2 + h3), 0.0f);

        const float4* w2row = reinterpret_cast<const float4*>(sW2 + j * NCLASS);
#pragma unroll
        for (int c = 0; c < 4; c++) {
            float4 w2 = w2row[c];
            acc[4 * c + 0] = fmaf(hid, w2.x, acc[4 * c + 0]);
            acc[4 * c + 1] = fmaf(hid, w2.y, acc[4 * c + 1]);
            acc[4 * c + 2] = fmaf(hid, w2.z, acc[4 * c + 2]);
            acc[4 * c + 3] = fmaf(hid, w2.w, acc[4 * c + 3]);
        }
    }

    float4* o = reinterpret_cast<float4*>(out + (long long)node * NCLASS);
#pragma unroll
    for (int c = 0; c < 4; c++)
        o[c] = make_float4(acc[4 * c], acc[4 * c + 1], acc[4 * c + 2], acc[4 * c + 3]);
}

// ---------------------------------------------------------------------------
// Launch.  Inputs (metadata order): x, edge_index(int32), eps, W1, b1, W2, b2
// ---------------------------------------------------------------------------
extern "C" void kernel_launch(void* const* d_in, const int* in_sizes, int n_in,
                              void* d_out, int out_size) {
    const float* x   = (const float*)d_in[0];
    const int*   ei  = (const int*)d_in[1];
    const float* eps = (const float*)d_in[2];
    const float* W1  = (const float*)d_in[3];
    const float* b1  = (const float*)d_in[4];
    const float* W2  = (const float*)d_in[5];
    const float* b2  = (const float*)d_in[6];
    float*       out = (float*)d_out;

    int n_nodes = in_sizes[0] / NFEAT;
    int n_edges = in_sizes[1] / 2;

    float *agg; int *counts, *row_start, *cursor, *csr_src, *bsum, *bpre;
    cudaGetSymbolAddress((void**)&agg,       g_agg);
    cudaGetSymbolAddress((void**)&counts,    g_counts);
    cudaGetSymbolAddress((void**)&row_start, g_row_start);
    cudaGetSymbolAddress((void**)&cursor,    g_cursor);
    cudaGetSymbolAddress((void**)&csr_src,   g_csr_src);
    cudaGetSymbolAddress((void**)&bsum,      g_bsum);
    cudaGetSymbolAddress((void**)&bpre,      g_bpre);

    int nb = (n_nodes + SCAN_B - 1) / SCAN_B;

    // --- CSR build ---
    zero_counts_kernel<<<(n_nodes + 255) / 256, 256>>>(counts, n_nodes);
    hist_kernel<<<(n_edges + 255) / 256, 256>>>(ei, counts, n_edges, n_nodes);
    scan1_kernel<<<nb, SCAN_B>>>(counts, bsum, n_nodes);
    scan2_kernel<<<1, 32>>>(bsum, bpre, nb);
    scan3_kernel<<<nb, SCAN_B>>>(counts, bpre, row_start, cursor, n_nodes);
    permute_kernel<<<(n_edges + 255) / 256, 256>>>(ei, cursor, csr_src, n_edges, n_nodes);

    // --- aggregation (pull, no atomics) ---
    long long gthreads = (long long)n_nodes * 16;
    gather_kernel<<<(int)((gthreads + 255) / 256), 256>>>(x, row_start, csr_src, eps, agg, n_nodes);

    // --- MLP ---
    mlp_kernel<<<(n_nodes + 127) / 128, 128>>>(agg, W1, b1, W2, b2, out, n_nodes);
}